// round 5
// baseline (speedup 1.0000x reference)
#include <cuda_runtime.h>
#include <stdint.h>
#include <math.h>

#define DD   1024
#define NH   16
#define HDIM 64
#define BB   2
#define LL   2048
#define MTOK (BB*LL)   // 4096

// ---------------- scratch (device globals; no allocations allowed) ----------
__device__ float g_Wc[3][DD*DD];            // combined weights W^T @ R
__device__ float g_Q[BB*NH*LL*HDIM];        // [b][h][l][d], pre-scaled by ent/8
__device__ float g_K[BB*NH*LL*HDIM];
__device__ float g_V[BB*NH*LL*HDIM];
__device__ float g_O[MTOK*DD];              // attention out in (B,L,D)

// ---------------- tf32 helpers ----------------------------------------------
__device__ __forceinline__ uint32_t f2tf32(float x) {
    uint32_t u;
    asm("cvt.rna.tf32.f32 %0, %1;" : "=r"(u) : "f"(x));
    return u;
}
__device__ __forceinline__ float tfr(float x) { return __uint_as_float(f2tf32(x)); }

__device__ __forceinline__ void mma8(float d[4], const uint32_t a[4], const uint32_t b[2]) {
    asm volatile(
        "mma.sync.aligned.m16n8k8.row.col.f32.tf32.tf32.f32 "
        "{%0,%1,%2,%3}, {%4,%5,%6,%7}, {%8,%9}, {%0,%1,%2,%3};"
        : "+f"(d[0]), "+f"(d[1]), "+f"(d[2]), "+f"(d[3])
        : "r"(a[0]), "r"(a[1]), "r"(a[2]), "r"(a[3]), "r"(b[0]), "r"(b[1]));
}

// ============================================================================
// Kernel 1: Wc[z] = W[z]^T @ R  (TN). 128x128x16 tiles, tf32 mma.
// A stored [k][m] (direct row copy of W), B stored [k][n].
// ============================================================================
__global__ __launch_bounds__(256) void combine_tf32(
    const float* __restrict__ Wq, const float* __restrict__ Wk,
    const float* __restrict__ Wv, const float* __restrict__ R)
{
    const float* W = (blockIdx.z == 0) ? Wq : ((blockIdx.z == 1) ? Wk : Wv);
    float* C = g_Wc[blockIdx.z];

    __shared__ float At[16][136];   // At[k][m]
    __shared__ float Bt[16][136];   // Bt[k][n]

    const int tid = threadIdx.x, lane = tid & 31, g = lane >> 2, t = lane & 3;
    const int warp = tid >> 5, wm = warp >> 2, wn = warp & 3;
    const int i0 = blockIdx.y * 128, j0 = blockIdx.x * 128;

    float acc[4][4][4] = {};

    for (int kt = 0; kt < DD; kt += 16) {
        #pragma unroll
        for (int r = 0; r < 2; r++) {
            int idx = tid + r * 256;
            int k = idx >> 5, c = (idx & 31) * 4;
            float4 a4 = *(const float4*)&W[(size_t)(kt + k) * DD + i0 + c];
            float4 b4 = *(const float4*)&R[(size_t)(kt + k) * DD + j0 + c];
            *(float4*)&At[k][c] = make_float4(tfr(a4.x), tfr(a4.y), tfr(a4.z), tfr(a4.w));
            *(float4*)&Bt[k][c] = make_float4(tfr(b4.x), tfr(b4.y), tfr(b4.z), tfr(b4.w));
        }
        __syncthreads();
        #pragma unroll
        for (int ks = 0; ks < 2; ks++) {
            const int kk = ks * 8 + t;
            uint32_t af[4][4], bf[4][2];
            #pragma unroll
            for (int mi = 0; mi < 4; mi++) {
                int mb = wm * 64 + mi * 16;
                af[mi][0] = __float_as_uint(At[kk][mb + g]);
                af[mi][1] = __float_as_uint(At[kk][mb + 8 + g]);
                af[mi][2] = __float_as_uint(At[kk + 4][mb + g]);
                af[mi][3] = __float_as_uint(At[kk + 4][mb + 8 + g]);
            }
            #pragma unroll
            for (int ni = 0; ni < 4; ni++) {
                int nb = wn * 32 + ni * 8;
                bf[ni][0] = __float_as_uint(Bt[kk][nb + g]);
                bf[ni][1] = __float_as_uint(Bt[kk + 4][nb + g]);
            }
            #pragma unroll
            for (int mi = 0; mi < 4; mi++)
                #pragma unroll
                for (int ni = 0; ni < 4; ni++)
                    mma8(acc[mi][ni], af[mi], bf[ni]);
        }
        __syncthreads();
    }

    #pragma unroll
    for (int mi = 0; mi < 4; mi++) {
        int row0 = i0 + wm * 64 + mi * 16 + g;
        #pragma unroll
        for (int ni = 0; ni < 4; ni++) {
            int col = j0 + wn * 32 + ni * 8 + 2 * t;
            *(float2*)&C[(size_t)row0 * DD + col] =
                make_float2(acc[mi][ni][0], acc[mi][ni][1]);
            *(float2*)&C[(size_t)(row0 + 8) * DD + col] =
                make_float2(acc[mi][ni][2], acc[mi][ni][3]);
        }
    }
}

// ============================================================================
// Kernel 2: P = X @ Wc[z] (NN), scatter into [b][h][l][d]; Q scaled by ent/8.
// A stored [m][k] pad 20, B stored [k][n] pad 136.
// ============================================================================
__global__ __launch_bounds__(256) void qkv_tf32(
    const float* __restrict__ X, const float* __restrict__ ent)
{
    const int z = blockIdx.z;
    const float* Wc = g_Wc[z];
    float* Out = (z == 0) ? g_Q : ((z == 1) ? g_K : g_V);

    __shared__ float As[128][20];
    __shared__ float Bt[16][136];

    const int tid = threadIdx.x, lane = tid & 31, g = lane >> 2, t = lane & 3;
    const int warp = tid >> 5, wm = warp >> 2, wn = warp & 3;
    const int m0 = blockIdx.y * 128, j0 = blockIdx.x * 128;
    const int b = m0 >> 11;   // 128-row tile never crosses a batch boundary

    float acc[4][4][4] = {};

    for (int kt = 0; kt < DD; kt += 16) {
        #pragma unroll
        for (int r = 0; r < 2; r++) {
            int idx = tid + r * 256;
            int ma = idx >> 2, ca = (idx & 3) * 4;
            float4 a4 = *(const float4*)&X[(size_t)(m0 + ma) * DD + kt + ca];
            *(float4*)&As[ma][ca] = make_float4(tfr(a4.x), tfr(a4.y), tfr(a4.z), tfr(a4.w));
            int kb = idx >> 5, cb = (idx & 31) * 4;
            float4 b4 = *(const float4*)&Wc[(size_t)(kt + kb) * DD + j0 + cb];
            *(float4*)&Bt[kb][cb] = make_float4(tfr(b4.x), tfr(b4.y), tfr(b4.z), tfr(b4.w));
        }
        __syncthreads();
        #pragma unroll
        for (int ks = 0; ks < 2; ks++) {
            const int kk = ks * 8 + t;
            uint32_t af[4][4], bf[4][2];
            #pragma unroll
            for (int mi = 0; mi < 4; mi++) {
                int mb = wm * 64 + mi * 16;
                af[mi][0] = __float_as_uint(As[mb + g][kk]);
                af[mi][1] = __float_as_uint(As[mb + 8 + g][kk]);
                af[mi][2] = __float_as_uint(As[mb + g][kk + 4]);
                af[mi][3] = __float_as_uint(As[mb + 8 + g][kk + 4]);
            }
            #pragma unroll
            for (int ni = 0; ni < 4; ni++) {
                int nb = wn * 32 + ni * 8;
                bf[ni][0] = __float_as_uint(Bt[kk][nb + g]);
                bf[ni][1] = __float_as_uint(Bt[kk + 4][nb + g]);
            }
            #pragma unroll
            for (int mi = 0; mi < 4; mi++)
                #pragma unroll
                for (int ni = 0; ni < 4; ni++)
                    mma8(acc[mi][ni], af[mi], bf[ni]);
        }
        __syncthreads();
    }

    #pragma unroll
    for (int ni = 0; ni < 4; ni++) {
        int n = j0 + wn * 32 + ni * 8 + 2 * t;
        int h = n >> 6, d = n & 63;
        float s = (z == 0) ? (ent[h] * 0.125f) : 1.0f;
        #pragma unroll
        for (int mi = 0; mi < 4; mi++) {
            int m = m0 + wm * 64 + mi * 16 + g;
            int l = m & (LL - 1);
            size_t base = (((size_t)(b * NH + h)) * LL + l) * HDIM + d;
            *(float2*)&Out[base] =
                make_float2(acc[mi][ni][0] * s, acc[mi][ni][1] * s);
            *(float2*)&Out[base + 8 * HDIM] =
                make_float2(acc[mi][ni][2] * s, acc[mi][ni][3] * s);
        }
    }
}

// ============================================================================
// Kernel 3: flash attention, tf32 mma. 256 thr = 8 warps x 16 q-rows.
// Key tiles of 64. Q frags register-resident; P round-trips through
// warp-private smem to convert C-layout -> A-layout.
// ============================================================================
#define KS_STR 68
#define VS_STR 72
#define PS_STR 68
#define FL_SMEM ((64*KS_STR + 64*VS_STR + 8*16*PS_STR) * 4)

__global__ __launch_bounds__(256) void flash_tf32()
{
    extern __shared__ float sm[];
    float* Ksm = sm;                       // [64][68]
    float* Vsm = sm + 64 * KS_STR;         // [64][72]
    const int tid = threadIdx.x, lane = tid & 31, g = lane >> 2, t = lane & 3;
    const int warp = tid >> 5;
    float* Pw = sm + 64 * KS_STR + 64 * VS_STR + warp * 16 * PS_STR;

    const int bh = blockIdx.y;             // = b*NH + h
    const size_t head_off = (size_t)bh * LL * HDIM;
    const float* Qb = g_Q + head_off;
    const float* Kb = g_K + head_off;
    const float* Vb = g_V + head_off;
    const int q0 = blockIdx.x * 128 + warp * 16;

    // Q fragments (tf32), resident in registers: 8 k-steps x 4 regs
    uint32_t qa[8][4];
    #pragma unroll
    for (int ks = 0; ks < 8; ks++) {
        qa[ks][0] = f2tf32(Qb[(size_t)(q0 + g) * HDIM + ks * 8 + t]);
        qa[ks][1] = f2tf32(Qb[(size_t)(q0 + 8 + g) * HDIM + ks * 8 + t]);
        qa[ks][2] = f2tf32(Qb[(size_t)(q0 + g) * HDIM + ks * 8 + t + 4]);
        qa[ks][3] = f2tf32(Qb[(size_t)(q0 + 8 + g) * HDIM + ks * 8 + t + 4]);
    }

    float o[8][4] = {};
    float m0v = -1e30f, m1v = -1e30f, l0 = 0.0f, l1 = 0.0f;

    for (int k0 = 0; k0 < LL; k0 += 64) {
        __syncthreads();
        // cooperative load + tf32-round of K,V tiles (64x64 each)
        #pragma unroll
        for (int r = 0; r < 4; r++) {
            int idx = tid + r * 256;
            int row = idx >> 4, c = (idx & 15) * 4;
            float4 k4 = *(const float4*)&Kb[(size_t)(k0 + row) * HDIM + c];
            float4 v4 = *(const float4*)&Vb[(size_t)(k0 + row) * HDIM + c];
            *(float4*)&Ksm[row * KS_STR + c] =
                make_float4(tfr(k4.x), tfr(k4.y), tfr(k4.z), tfr(k4.w));
            *(float4*)&Vsm[row * VS_STR + c] =
                make_float4(tfr(v4.x), tfr(v4.y), tfr(v4.z), tfr(v4.w));
        }
        __syncthreads();

        // S = Q @ K^T : 16 x 64 per warp
        float s[8][4] = {};
        #pragma unroll
        for (int ks = 0; ks < 8; ks++) {
            #pragma unroll
            for (int nt = 0; nt < 8; nt++) {
                uint32_t bf[2];
                bf[0] = __float_as_uint(Ksm[(nt * 8 + g) * KS_STR + ks * 8 + t]);
                bf[1] = __float_as_uint(Ksm[(nt * 8 + g) * KS_STR + ks * 8 + t + 4]);
                mma8(s[nt], qa[ks], bf);
            }
        }

        // online softmax (rows g and g+8, spread over 4 lanes each)
        float rmax0 = -1e30f, rmax1 = -1e30f;
        #pragma unroll
        for (int nt = 0; nt < 8; nt++) {
            rmax0 = fmaxf(rmax0, fmaxf(s[nt][0], s[nt][1]));
            rmax1 = fmaxf(rmax1, fmaxf(s[nt][2], s[nt][3]));
        }
        rmax0 = fmaxf(rmax0, __shfl_xor_sync(0xffffffffu, rmax0, 1));
        rmax0 = fmaxf(rmax0, __shfl_xor_sync(0xffffffffu, rmax0, 2));
        rmax1 = fmaxf(rmax1, __shfl_xor_sync(0xffffffffu, rmax1, 1));
        rmax1 = fmaxf(rmax1, __shfl_xor_sync(0xffffffffu, rmax1, 2));

        float nm0 = fmaxf(m0v, rmax0), nm1 = fmaxf(m1v, rmax1);
        float c0 = __expf(m0v - nm0), c1 = __expf(m1v - nm1);
        m0v = nm0; m1v = nm1;

        float sum0 = 0.0f, sum1 = 0.0f;
        #pragma unroll
        for (int nt = 0; nt < 8; nt++) {
            s[nt][0] = __expf(s[nt][0] - m0v); sum0 += s[nt][0];
            s[nt][1] = __expf(s[nt][1] - m0v); sum0 += s[nt][1];
            s[nt][2] = __expf(s[nt][2] - m1v); sum1 += s[nt][2];
            s[nt][3] = __expf(s[nt][3] - m1v); sum1 += s[nt][3];
        }
        sum0 += __shfl_xor_sync(0xffffffffu, sum0, 1);
        sum0 += __shfl_xor_sync(0xffffffffu, sum0, 2);
        sum1 += __shfl_xor_sync(0xffffffffu, sum1, 1);
        sum1 += __shfl_xor_sync(0xffffffffu, sum1, 2);
        l0 = l0 * c0 + sum0;
        l1 = l1 * c1 + sum1;

        #pragma unroll
        for (int nt = 0; nt < 8; nt++) {
            o[nt][0] *= c0; o[nt][1] *= c0;
            o[nt][2] *= c1; o[nt][3] *= c1;
        }

        // P: C-layout regs -> warp-private smem (tf32-rounded)
        #pragma unroll
        for (int nt = 0; nt < 8; nt++) {
            *(float2*)&Pw[g * PS_STR + nt * 8 + 2 * t] =
                make_float2(tfr(s[nt][0]), tfr(s[nt][1]));
            *(float2*)&Pw[(g + 8) * PS_STR + nt * 8 + 2 * t] =
                make_float2(tfr(s[nt][2]), tfr(s[nt][3]));
        }
        __syncwarp();

        // O += P @ V
        #pragma unroll
        for (int ks = 0; ks < 8; ks++) {
            uint32_t pa[4];
            pa[0] = __float_as_uint(Pw[g * PS_STR + ks * 8 + t]);
            pa[1] = __float_as_uint(Pw[(g + 8) * PS_STR + ks * 8 + t]);
            pa[2] = __float_as_uint(Pw[g * PS_STR + ks * 8 + t + 4]);
            pa[3] = __float_as_uint(Pw[(g + 8) * PS_STR + ks * 8 + t + 4]);
            #pragma unroll
            for (int nt = 0; nt < 8; nt++) {
                uint32_t bf[2];
                bf[0] = __float_as_uint(Vsm[(ks * 8 + t) * VS_STR + nt * 8 + g]);
                bf[1] = __float_as_uint(Vsm[(ks * 8 + t + 4) * VS_STR + nt * 8 + g]);
                mma8(o[nt], pa, bf);
            }
        }
        __syncwarp();
    }

    const int b = bh >> 4, h = bh & 15;
    float inv0 = 1.0f / l0, inv1 = 1.0f / l1;
    float* Ob0 = g_O + ((size_t)b * LL + q0 + g) * DD + h * HDIM;
    float* Ob1 = g_O + ((size_t)b * LL + q0 + 8 + g) * DD + h * HDIM;
    #pragma unroll
    for (int nt = 0; nt < 8; nt++) {
        int col = nt * 8 + 2 * t;
        *(float2*)&Ob0[col] = make_float2(o[nt][0] * inv0, o[nt][1] * inv0);
        *(float2*)&Ob1[col] = make_float2(o[nt][2] * inv1, o[nt][3] * inv1);
    }
}

// ============================================================================
// Kernel 4: Y = O @ Wo^T (NT). A [m][k] pad 20, B [n][k] pad 20.
// ============================================================================
__global__ __launch_bounds__(256) void out_tf32(
    const float* __restrict__ Wo, float* __restrict__ Y)
{
    __shared__ float As[128][20];
    __shared__ float Bs[128][20];

    const int tid = threadIdx.x, lane = tid & 31, g = lane >> 2, t = lane & 3;
    const int warp = tid >> 5, wm = warp >> 2, wn = warp & 3;
    const int m0 = blockIdx.y * 128, j0 = blockIdx.x * 128;

    float acc[4][4][4] = {};

    for (int kt = 0; kt < DD; kt += 16) {
        #pragma unroll
        for (int r = 0; r < 2; r++) {
            int idx = tid + r * 256;
            int row = idx >> 2, c = (idx & 3) * 4;
            float4 a4 = *(const float4*)&g_O[(size_t)(m0 + row) * DD + kt + c];
            *(float4*)&As[row][c] = make_float4(tfr(a4.x), tfr(a4.y), tfr(a4.z), tfr(a4.w));
            float4 b4 = *(const float4*)&Wo[(size_t)(j0 + row) * DD + kt + c];
            *(float4*)&Bs[row][c] = make_float4(tfr(b4.x), tfr(b4.y), tfr(b4.z), tfr(b4.w));
        }
        __syncthreads();
        #pragma unroll
        for (int ks = 0; ks < 2; ks++) {
            const int kk = ks * 8 + t;
            uint32_t af[4][4], bf[4][2];
            #pragma unroll
            for (int mi = 0; mi < 4; mi++) {
                int mb = wm * 64 + mi * 16;
                af[mi][0] = __float_as_uint(As[mb + g][kk]);
                af[mi][1] = __float_as_uint(As[mb + 8 + g][kk]);
                af[mi][2] = __float_as_uint(As[mb + g][kk + 4]);
                af[mi][3] = __float_as_uint(As[mb + 8 + g][kk + 4]);
            }
            #pragma unroll
            for (int ni = 0; ni < 4; ni++) {
                int nb = wn * 32 + ni * 8;
                bf[ni][0] = __float_as_uint(Bs[nb + g][kk]);
                bf[ni][1] = __float_as_uint(Bs[nb + g][kk + 4]);
            }
            #pragma unroll
            for (int mi = 0; mi < 4; mi++)
                #pragma unroll
                for (int ni = 0; ni < 4; ni++)
                    mma8(acc[mi][ni], af[mi], bf[ni]);
        }
        __syncthreads();
    }

    #pragma unroll
    for (int mi = 0; mi < 4; mi++) {
        int row0 = m0 + wm * 64 + mi * 16 + g;
        #pragma unroll
        for (int ni = 0; ni < 4; ni++) {
            int col = j0 + wn * 32 + ni * 8 + 2 * t;
            *(float2*)&Y[(size_t)row0 * DD + col] =
                make_float2(acc[mi][ni][0], acc[mi][ni][1]);
            *(float2*)&Y[(size_t)(row0 + 8) * DD + col] =
                make_float2(acc[mi][ni][2], acc[mi][ni][3]);
        }
    }
}

// ============================================================================
// launch
// ============================================================================
extern "C" void kernel_launch(void* const* d_in, const int* in_sizes, int n_in,
                              void* d_out, int out_size)
{
    const float* X   = (const float*)d_in[0];
    const float* R   = (const float*)d_in[1];
    const float* ent = (const float*)d_in[2];
    const float* Wq  = (const float*)d_in[3];
    const float* Wk  = (const float*)d_in[4];
    const float* Wv  = (const float*)d_in[5];
    const float* Wo  = (const float*)d_in[6];
    float* Y = (float*)d_out;

    cudaFuncSetAttribute(flash_tf32,
                         cudaFuncAttributeMaxDynamicSharedMemorySize, FL_SMEM);

    combine_tf32<<<dim3(8, 8, 3), 256>>>(Wq, Wk, Wv, R);
    qkv_tf32<<<dim3(8, MTOK / 128, 3), 256>>>(X, ent);
    flash_tf32<<<dim3(LL / 128, BB * NH), 256, FL_SMEM>>>();
    out_tf32<<<dim3(8, MTOK / 128), 256>>>(Wo, Y);
}

// round 6
// speedup vs baseline: 1.0008x; 1.0008x over previous
#include <cuda_runtime.h>
#include <stdint.h>
#include <math.h>

#define DD   1024
#define NH   16
#define HDIM 64
#define BB   2
#define LL   2048
#define MTOK (BB*LL)   // 4096

// ---------------- scratch (device globals; no allocations allowed) ----------
__device__ float g_Wc[3][DD*DD];            // combined weights W^T @ R
__device__ float g_Q[BB*NH*LL*HDIM];        // [b][h][l][d], pre-scaled by ent/8
__device__ float g_K[BB*NH*LL*HDIM];
__device__ float g_V[BB*NH*LL*HDIM];
__device__ float g_O[MTOK*DD];              // attention out in (B,L,D)

// ---------------- tf32 helpers ----------------------------------------------
__device__ __forceinline__ uint32_t f2tf32(float x) {
    uint32_t u;
    asm("cvt.rna.tf32.f32 %0, %1;" : "=r"(u) : "f"(x));
    return u;
}
__device__ __forceinline__ float tfr(float x) { return __uint_as_float(f2tf32(x)); }

__device__ __forceinline__ void mma8(float d[4], const uint32_t a[4], const uint32_t b[2]) {
    asm volatile(
        "mma.sync.aligned.m16n8k8.row.col.f32.tf32.tf32.f32 "
        "{%0,%1,%2,%3}, {%4,%5,%6,%7}, {%8,%9}, {%0,%1,%2,%3};"
        : "+f"(d[0]), "+f"(d[1]), "+f"(d[2]), "+f"(d[3])
        : "r"(a[0]), "r"(a[1]), "r"(a[2]), "r"(a[3]), "r"(b[0]), "r"(b[1]));
}

// ============================================================================
// Kernel 1: Wc[z] = W[z]^T @ R  (TN). 128x128x16 tiles, tf32 mma.
// A stored [k][m] (direct row copy of W), B stored [k][n].
// ============================================================================
__global__ __launch_bounds__(256) void combine_tf32(
    const float* __restrict__ Wq, const float* __restrict__ Wk,
    const float* __restrict__ Wv, const float* __restrict__ R)
{
    const float* W = (blockIdx.z == 0) ? Wq : ((blockIdx.z == 1) ? Wk : Wv);
    float* C = g_Wc[blockIdx.z];

    __shared__ float At[16][136];   // At[k][m]
    __shared__ float Bt[16][136];   // Bt[k][n]

    const int tid = threadIdx.x, lane = tid & 31, g = lane >> 2, t = lane & 3;
    const int warp = tid >> 5, wm = warp >> 2, wn = warp & 3;
    const int i0 = blockIdx.y * 128, j0 = blockIdx.x * 128;

    float acc[4][4][4] = {};

    for (int kt = 0; kt < DD; kt += 16) {
        #pragma unroll
        for (int r = 0; r < 2; r++) {
            int idx = tid + r * 256;
            int k = idx >> 5, c = (idx & 31) * 4;
            float4 a4 = *(const float4*)&W[(size_t)(kt + k) * DD + i0 + c];
            float4 b4 = *(const float4*)&R[(size_t)(kt + k) * DD + j0 + c];
            *(float4*)&At[k][c] = make_float4(tfr(a4.x), tfr(a4.y), tfr(a4.z), tfr(a4.w));
            *(float4*)&Bt[k][c] = make_float4(tfr(b4.x), tfr(b4.y), tfr(b4.z), tfr(b4.w));
        }
        __syncthreads();
        #pragma unroll
        for (int ks = 0; ks < 2; ks++) {
            const int kk = ks * 8 + t;
            uint32_t af[4][4], bf[4][2];
            #pragma unroll
            for (int mi = 0; mi < 4; mi++) {
                int mb = wm * 64 + mi * 16;
                af[mi][0] = __float_as_uint(At[kk][mb + g]);
                af[mi][1] = __float_as_uint(At[kk][mb + 8 + g]);
                af[mi][2] = __float_as_uint(At[kk + 4][mb + g]);
                af[mi][3] = __float_as_uint(At[kk + 4][mb + 8 + g]);
            }
            #pragma unroll
            for (int ni = 0; ni < 4; ni++) {
                int nb = wn * 32 + ni * 8;
                bf[ni][0] = __float_as_uint(Bt[kk][nb + g]);
                bf[ni][1] = __float_as_uint(Bt[kk + 4][nb + g]);
            }
            #pragma unroll
            for (int mi = 0; mi < 4; mi++)
                #pragma unroll
                for (int ni = 0; ni < 4; ni++)
                    mma8(acc[mi][ni], af[mi], bf[ni]);
        }
        __syncthreads();
    }

    #pragma unroll
    for (int mi = 0; mi < 4; mi++) {
        int row0 = i0 + wm * 64 + mi * 16 + g;
        #pragma unroll
        for (int ni = 0; ni < 4; ni++) {
            int col = j0 + wn * 32 + ni * 8 + 2 * t;
            *(float2*)&C[(size_t)row0 * DD + col] =
                make_float2(acc[mi][ni][0], acc[mi][ni][1]);
            *(float2*)&C[(size_t)(row0 + 8) * DD + col] =
                make_float2(acc[mi][ni][2], acc[mi][ni][3]);
        }
    }
}

// ============================================================================
// Kernel 2: P = X @ Wc[z] (NN), scatter into [b][h][l][d]; Q scaled by ent/8.
// A stored [m][k] pad 20, B stored [k][n] pad 136.
// ============================================================================
__global__ __launch_bounds__(256) void qkv_tf32(
    const float* __restrict__ X, const float* __restrict__ ent)
{
    const int z = blockIdx.z;
    const float* Wc = g_Wc[z];
    float* Out = (z == 0) ? g_Q : ((z == 1) ? g_K : g_V);

    __shared__ float As[128][20];
    __shared__ float Bt[16][136];

    const int tid = threadIdx.x, lane = tid & 31, g = lane >> 2, t = lane & 3;
    const int warp = tid >> 5, wm = warp >> 2, wn = warp & 3;
    const int m0 = blockIdx.y * 128, j0 = blockIdx.x * 128;
    const int b = m0 >> 11;   // 128-row tile never crosses a batch boundary

    float acc[4][4][4] = {};

    for (int kt = 0; kt < DD; kt += 16) {
        #pragma unroll
        for (int r = 0; r < 2; r++) {
            int idx = tid + r * 256;
            int ma = idx >> 2, ca = (idx & 3) * 4;
            float4 a4 = *(const float4*)&X[(size_t)(m0 + ma) * DD + kt + ca];
            *(float4*)&As[ma][ca] = make_float4(tfr(a4.x), tfr(a4.y), tfr(a4.z), tfr(a4.w));
            int kb = idx >> 5, cb = (idx & 31) * 4;
            float4 b4 = *(const float4*)&Wc[(size_t)(kt + kb) * DD + j0 + cb];
            *(float4*)&Bt[kb][cb] = make_float4(tfr(b4.x), tfr(b4.y), tfr(b4.z), tfr(b4.w));
        }
        __syncthreads();
        #pragma unroll
        for (int ks = 0; ks < 2; ks++) {
            const int kk = ks * 8 + t;
            uint32_t af[4][4], bf[4][2];
            #pragma unroll
            for (int mi = 0; mi < 4; mi++) {
                int mb = wm * 64 + mi * 16;
                af[mi][0] = __float_as_uint(As[mb + g][kk]);
                af[mi][1] = __float_as_uint(As[mb + 8 + g][kk]);
                af[mi][2] = __float_as_uint(As[mb + g][kk + 4]);
                af[mi][3] = __float_as_uint(As[mb + 8 + g][kk + 4]);
            }
            #pragma unroll
            for (int ni = 0; ni < 4; ni++) {
                int nb = wn * 32 + ni * 8;
                bf[ni][0] = __float_as_uint(Bt[kk][nb + g]);
                bf[ni][1] = __float_as_uint(Bt[kk + 4][nb + g]);
            }
            #pragma unroll
            for (int mi = 0; mi < 4; mi++)
                #pragma unroll
                for (int ni = 0; ni < 4; ni++)
                    mma8(acc[mi][ni], af[mi], bf[ni]);
        }
        __syncthreads();
    }

    #pragma unroll
    for (int ni = 0; ni < 4; ni++) {
        int n = j0 + wn * 32 + ni * 8 + 2 * t;
        int h = n >> 6, d = n & 63;
        float s = (z == 0) ? (ent[h] * 0.125f) : 1.0f;
        #pragma unroll
        for (int mi = 0; mi < 4; mi++) {
            int m = m0 + wm * 64 + mi * 16 + g;
            int l = m & (LL - 1);
            size_t base = (((size_t)(b * NH + h)) * LL + l) * HDIM + d;
            *(float2*)&Out[base] =
                make_float2(acc[mi][ni][0] * s, acc[mi][ni][1] * s);
            *(float2*)&Out[base + 8 * HDIM] =
                make_float2(acc[mi][ni][2] * s, acc[mi][ni][3] * s);
        }
    }
}

// ============================================================================
// Kernel 3: flash attention, tf32 mma. 256 thr = 8 warps x 16 q-rows.
// Key tiles of 64. Q frags register-resident; P round-trips through
// warp-private smem to convert C-layout -> A-layout.
// ============================================================================
#define KS_STR 68
#define VS_STR 72
#define PS_STR 68
#define FL_SMEM ((64*KS_STR + 64*VS_STR + 8*16*PS_STR) * 4)

__global__ __launch_bounds__(256) void flash_tf32()
{
    extern __shared__ float sm[];
    float* Ksm = sm;                       // [64][68]
    float* Vsm = sm + 64 * KS_STR;         // [64][72]
    const int tid = threadIdx.x, lane = tid & 31, g = lane >> 2, t = lane & 3;
    const int warp = tid >> 5;
    float* Pw = sm + 64 * KS_STR + 64 * VS_STR + warp * 16 * PS_STR;

    const int bh = blockIdx.y;             // = b*NH + h
    const size_t head_off = (size_t)bh * LL * HDIM;
    const float* Qb = g_Q + head_off;
    const float* Kb = g_K + head_off;
    const float* Vb = g_V + head_off;
    const int q0 = blockIdx.x * 128 + warp * 16;

    // Q fragments (tf32), resident in registers: 8 k-steps x 4 regs
    uint32_t qa[8][4];
    #pragma unroll
    for (int ks = 0; ks < 8; ks++) {
        qa[ks][0] = f2tf32(Qb[(size_t)(q0 + g) * HDIM + ks * 8 + t]);
        qa[ks][1] = f2tf32(Qb[(size_t)(q0 + 8 + g) * HDIM + ks * 8 + t]);
        qa[ks][2] = f2tf32(Qb[(size_t)(q0 + g) * HDIM + ks * 8 + t + 4]);
        qa[ks][3] = f2tf32(Qb[(size_t)(q0 + 8 + g) * HDIM + ks * 8 + t + 4]);
    }

    float o[8][4] = {};
    float m0v = -1e30f, m1v = -1e30f, l0 = 0.0f, l1 = 0.0f;

    for (int k0 = 0; k0 < LL; k0 += 64) {
        __syncthreads();
        // cooperative load + tf32-round of K,V tiles (64x64 each)
        #pragma unroll
        for (int r = 0; r < 4; r++) {
            int idx = tid + r * 256;
            int row = idx >> 4, c = (idx & 15) * 4;
            float4 k4 = *(const float4*)&Kb[(size_t)(k0 + row) * HDIM + c];
            float4 v4 = *(const float4*)&Vb[(size_t)(k0 + row) * HDIM + c];
            *(float4*)&Ksm[row * KS_STR + c] =
                make_float4(tfr(k4.x), tfr(k4.y), tfr(k4.z), tfr(k4.w));
            *(float4*)&Vsm[row * VS_STR + c] =
                make_float4(tfr(v4.x), tfr(v4.y), tfr(v4.z), tfr(v4.w));
        }
        __syncthreads();

        // S = Q @ K^T : 16 x 64 per warp
        float s[8][4] = {};
        #pragma unroll
        for (int ks = 0; ks < 8; ks++) {
            #pragma unroll
            for (int nt = 0; nt < 8; nt++) {
                uint32_t bf[2];
                bf[0] = __float_as_uint(Ksm[(nt * 8 + g) * KS_STR + ks * 8 + t]);
                bf[1] = __float_as_uint(Ksm[(nt * 8 + g) * KS_STR + ks * 8 + t + 4]);
                mma8(s[nt], qa[ks], bf);
            }
        }

        // online softmax (rows g and g+8, spread over 4 lanes each)
        float rmax0 = -1e30f, rmax1 = -1e30f;
        #pragma unroll
        for (int nt = 0; nt < 8; nt++) {
            rmax0 = fmaxf(rmax0, fmaxf(s[nt][0], s[nt][1]));
            rmax1 = fmaxf(rmax1, fmaxf(s[nt][2], s[nt][3]));
        }
        rmax0 = fmaxf(rmax0, __shfl_xor_sync(0xffffffffu, rmax0, 1));
        rmax0 = fmaxf(rmax0, __shfl_xor_sync(0xffffffffu, rmax0, 2));
        rmax1 = fmaxf(rmax1, __shfl_xor_sync(0xffffffffu, rmax1, 1));
        rmax1 = fmaxf(rmax1, __shfl_xor_sync(0xffffffffu, rmax1, 2));

        float nm0 = fmaxf(m0v, rmax0), nm1 = fmaxf(m1v, rmax1);
        float c0 = __expf(m0v - nm0), c1 = __expf(m1v - nm1);
        m0v = nm0; m1v = nm1;

        float sum0 = 0.0f, sum1 = 0.0f;
        #pragma unroll
        for (int nt = 0; nt < 8; nt++) {
            s[nt][0] = __expf(s[nt][0] - m0v); sum0 += s[nt][0];
            s[nt][1] = __expf(s[nt][1] - m0v); sum0 += s[nt][1];
            s[nt][2] = __expf(s[nt][2] - m1v); sum1 += s[nt][2];
            s[nt][3] = __expf(s[nt][3] - m1v); sum1 += s[nt][3];
        }
        sum0 += __shfl_xor_sync(0xffffffffu, sum0, 1);
        sum0 += __shfl_xor_sync(0xffffffffu, sum0, 2);
        sum1 += __shfl_xor_sync(0xffffffffu, sum1, 1);
        sum1 += __shfl_xor_sync(0xffffffffu, sum1, 2);
        l0 = l0 * c0 + sum0;
        l1 = l1 * c1 + sum1;

        #pragma unroll
        for (int nt = 0; nt < 8; nt++) {
            o[nt][0] *= c0; o[nt][1] *= c0;
            o[nt][2] *= c1; o[nt][3] *= c1;
        }

        // P: C-layout regs -> warp-private smem (tf32-rounded)
        #pragma unroll
        for (int nt = 0; nt < 8; nt++) {
            *(float2*)&Pw[g * PS_STR + nt * 8 + 2 * t] =
                make_float2(tfr(s[nt][0]), tfr(s[nt][1]));
            *(float2*)&Pw[(g + 8) * PS_STR + nt * 8 + 2 * t] =
                make_float2(tfr(s[nt][2]), tfr(s[nt][3]));
        }
        __syncwarp();

        // O += P @ V
        #pragma unroll
        for (int ks = 0; ks < 8; ks++) {
            uint32_t pa[4];
            pa[0] = __float_as_uint(Pw[g * PS_STR + ks * 8 + t]);
            pa[1] = __float_as_uint(Pw[(g + 8) * PS_STR + ks * 8 + t]);
            pa[2] = __float_as_uint(Pw[g * PS_STR + ks * 8 + t + 4]);
            pa[3] = __float_as_uint(Pw[(g + 8) * PS_STR + ks * 8 + t + 4]);
            #pragma unroll
            for (int nt = 0; nt < 8; nt++) {
                uint32_t bf[2];
                bf[0] = __float_as_uint(Vsm[(ks * 8 + t) * VS_STR + nt * 8 + g]);
                bf[1] = __float_as_uint(Vsm[(ks * 8 + t + 4) * VS_STR + nt * 8 + g]);
                mma8(o[nt], pa, bf);
            }
        }
        __syncwarp();
    }

    const int b = bh >> 4, h = bh & 15;
    float inv0 = 1.0f / l0, inv1 = 1.0f / l1;
    float* Ob0 = g_O + ((size_t)b * LL + q0 + g) * DD + h * HDIM;
    float* Ob1 = g_O + ((size_t)b * LL + q0 + 8 + g) * DD + h * HDIM;
    #pragma unroll
    for (int nt = 0; nt < 8; nt++) {
        int col = nt * 8 + 2 * t;
        *(float2*)&Ob0[col] = make_float2(o[nt][0] * inv0, o[nt][1] * inv0);
        *(float2*)&Ob1[col] = make_float2(o[nt][2] * inv1, o[nt][3] * inv1);
    }
}

// ============================================================================
// Kernel 4: Y = O @ Wo^T (NT). A [m][k] pad 20, B [n][k] pad 20.
// ============================================================================
__global__ __launch_bounds__(256) void out_tf32(
    const float* __restrict__ Wo, float* __restrict__ Y)
{
    __shared__ float As[128][20];
    __shared__ float Bs[128][20];

    const int tid = threadIdx.x, lane = tid & 31, g = lane >> 2, t = lane & 3;
    const int warp = tid >> 5, wm = warp >> 2, wn = warp & 3;
    const int m0 = blockIdx.y * 128, j0 = blockIdx.x * 128;

    float acc[4][4][4] = {};

    for (int kt = 0; kt < DD; kt += 16) {
        #pragma unroll
        for (int r = 0; r < 2; r++) {
            int idx = tid + r * 256;
            int row = idx >> 2, c = (idx & 3) * 4;
            float4 a4 = *(const float4*)&g_O[(size_t)(m0 + row) * DD + kt + c];
            *(float4*)&As[row][c] = make_float4(tfr(a4.x), tfr(a4.y), tfr(a4.z), tfr(a4.w));
            float4 b4 = *(const float4*)&Wo[(size_t)(j0 + row) * DD + kt + c];
            *(float4*)&Bs[row][c] = make_float4(tfr(b4.x), tfr(b4.y), tfr(b4.z), tfr(b4.w));
        }
        __syncthreads();
        #pragma unroll
        for (int ks = 0; ks < 2; ks++) {
            const int kk = ks * 8 + t;
            uint32_t af[4][4], bf[4][2];
            #pragma unroll
            for (int mi = 0; mi < 4; mi++) {
                int mb = wm * 64 + mi * 16;
                af[mi][0] = __float_as_uint(As[mb + g][kk]);
                af[mi][1] = __float_as_uint(As[mb + 8 + g][kk]);
                af[mi][2] = __float_as_uint(As[mb + g][kk + 4]);
                af[mi][3] = __float_as_uint(As[mb + 8 + g][kk + 4]);
            }
            #pragma unroll
            for (int ni = 0; ni < 4; ni++) {
                int nb = wn * 32 + ni * 8;
                bf[ni][0] = __float_as_uint(Bs[nb + g][kk]);
                bf[ni][1] = __float_as_uint(Bs[nb + g][kk + 4]);
            }
            #pragma unroll
            for (int mi = 0; mi < 4; mi++)
                #pragma unroll
                for (int ni = 0; ni < 4; ni++)
                    mma8(acc[mi][ni], af[mi], bf[ni]);
        }
        __syncthreads();
    }

    #pragma unroll
    for (int mi = 0; mi < 4; mi++) {
        int row0 = m0 + wm * 64 + mi * 16 + g;
        #pragma unroll
        for (int ni = 0; ni < 4; ni++) {
            int col = j0 + wn * 32 + ni * 8 + 2 * t;
            *(float2*)&Y[(size_t)row0 * DD + col] =
                make_float2(acc[mi][ni][0], acc[mi][ni][1]);
            *(float2*)&Y[(size_t)(row0 + 8) * DD + col] =
                make_float2(acc[mi][ni][2], acc[mi][ni][3]);
        }
    }
}

// ============================================================================
// launch
// ============================================================================
extern "C" void kernel_launch(void* const* d_in, const int* in_sizes, int n_in,
                              void* d_out, int out_size)
{
    const float* X   = (const float*)d_in[0];
    const float* R   = (const float*)d_in[1];
    const float* ent = (const float*)d_in[2];
    const float* Wq  = (const float*)d_in[3];
    const float* Wk  = (const float*)d_in[4];
    const float* Wv  = (const float*)d_in[5];
    const float* Wo  = (const float*)d_in[6];
    float* Y = (float*)d_out;

    cudaFuncSetAttribute(flash_tf32,
                         cudaFuncAttributeMaxDynamicSharedMemorySize, FL_SMEM);

    combine_tf32<<<dim3(8, 8, 3), 256>>>(Wq, Wk, Wv, R);
    qkv_tf32<<<dim3(8, MTOK / 128, 3), 256>>>(X, ent);
    flash_tf32<<<dim3(LL / 128, BB * NH), 256, FL_SMEM>>>();
    out_tf32<<<dim3(8, MTOK / 128), 256>>>(Wo, Y);
}